// round 1
// baseline (speedup 1.0000x reference)
#include <cuda_runtime.h>
#include <math.h>

#define NA 50000
#define NP 50000
#define EE 600000
#define HH 8
#define DD 16
#define CC 128
#define OUTC 16
#define FA 256
#define FP 128
#define EPSV 1e-5f

// ---------------- device scratch (static, no allocation) ----------------
__device__ float    g_h_a[(size_t)NA * CC];
__device__ float    g_h_p[(size_t)NP * CC];
__device__ float    g_as_ap[NA * HH];
__device__ float    g_ad_ap[NP * HH];
__device__ float    g_as_pp[NP * HH];
__device__ float    g_ad_pp[NP * HH];
__device__ float    g_alpha_ap[(size_t)EE * HH];
__device__ float    g_alpha_pp[(size_t)EE * HH];
__device__ unsigned g_segmax[2 * NP * HH];
__device__ float    g_denom[2 * NP * HH];
__device__ float    g_out01[2 * (size_t)NP * CC];   // [r][n][c]
__device__ float    g_wsum[2];
__device__ float    g_beta[2];
__device__ float    g_S1[CC];
__device__ float    g_S2[CC];
__device__ float    g_nA[CC];
__device__ float    g_nB[CC];

// ---------------- helpers ----------------
__device__ __forceinline__ unsigned fenc(float f) {
    unsigned u = __float_as_uint(f);
    return u ^ (unsigned)(((int)u >> 31) | 0x80000000);
}
__device__ __forceinline__ float fdec(unsigned u) {
    unsigned m = ((int)u < 0) ? 0x80000000u : 0xFFFFFFFFu;
    return __uint_as_float(u ^ m);
}

// ---------------- init: re-zero accumulators every call ----------------
__global__ void init_kernel() {
    int idx = blockIdx.x * blockDim.x + threadIdx.x;
    int stride = gridDim.x * blockDim.x;
    for (size_t i = idx; i < 2 * (size_t)NP * CC; i += stride) g_out01[i] = 0.f;
    for (int i = idx; i < 2 * NP * HH; i += stride) {
        g_denom[i] = 0.f;
        g_segmax[i] = 0x007FFFFFu;   // fenc(-inf)
    }
    if (idx < CC) { g_S1[idx] = 0.f; g_S2[idx] = 0.f; }
    if (idx < 2)  g_wsum[idx] = 0.f;
}

// ---------------- tiled fp32 GEMM: [N, KDIM] x [KDIM, 128] + bias ----------------
// BM=64, BN=128, BK=16, 256 threads, thread tile 8x4
template <int KDIM>
__global__ void gemm_proj_kernel(const float* __restrict__ X,
                                 const float* __restrict__ W,
                                 const float* __restrict__ bias,
                                 float* __restrict__ out, int Nrows) {
    __shared__ float As[16][68];
    __shared__ float Bs[16][128];
    int tid = threadIdx.x;
    int tx = tid & 31, ty = tid >> 5;
    int row0 = blockIdx.x * 64;

    float acc[8][4];
#pragma unroll
    for (int m = 0; m < 8; m++)
#pragma unroll
        for (int n = 0; n < 4; n++) acc[m][n] = 0.f;

    int ar = tid >> 2;            // 0..63
    int ak0 = (tid & 3) * 4;      // 0,4,8,12
    int bk = tid >> 4;            // 0..15
    int bc0 = (tid & 15) * 8;     // 0..120

    for (int k0 = 0; k0 < KDIM; k0 += 16) {
        int grow = row0 + ar;
        float4 av = make_float4(0.f, 0.f, 0.f, 0.f);
        if (grow < Nrows)
            av = *(const float4*)(X + (size_t)grow * KDIM + k0 + ak0);
        As[ak0 + 0][ar] = av.x; As[ak0 + 1][ar] = av.y;
        As[ak0 + 2][ar] = av.z; As[ak0 + 3][ar] = av.w;

        const float* wp = W + (size_t)(k0 + bk) * CC + bc0;
        float4 bv0 = *(const float4*)(wp);
        float4 bv1 = *(const float4*)(wp + 4);
        *(float4*)&Bs[bk][bc0] = bv0;
        *(float4*)&Bs[bk][bc0 + 4] = bv1;
        __syncthreads();

#pragma unroll
        for (int kk = 0; kk < 16; kk++) {
            float4 b4 = *(const float4*)&Bs[kk][tx * 4];
            float a[8];
#pragma unroll
            for (int m = 0; m < 8; m++) a[m] = As[kk][ty * 8 + m];
#pragma unroll
            for (int m = 0; m < 8; m++) {
                acc[m][0] += a[m] * b4.x;
                acc[m][1] += a[m] * b4.y;
                acc[m][2] += a[m] * b4.z;
                acc[m][3] += a[m] * b4.w;
            }
        }
        __syncthreads();
    }

    float4 bb = *(const float4*)(bias + tx * 4);
#pragma unroll
    for (int m = 0; m < 8; m++) {
        int grow = row0 + ty * 8 + m;
        if (grow < Nrows) {
            float4 v = make_float4(acc[m][0] + bb.x, acc[m][1] + bb.y,
                                   acc[m][2] + bb.z, acc[m][3] + bb.w);
            *(float4*)(out + (size_t)grow * CC + tx * 4) = v;
        }
    }
}

// ---------------- per-node-head attention logits: alpha[n,h] = <h[n,h,:], att[h,:]> ----------------
__global__ void alpha1_kernel(const float* __restrict__ Hm, const float* __restrict__ att,
                              float* __restrict__ out, int N) {
    __shared__ float a[CC];
    if (threadIdx.x < CC) a[threadIdx.x] = att[threadIdx.x];
    __syncthreads();
    int idx = blockIdx.x * blockDim.x + threadIdx.x;
    if (idx >= N * HH) return;
    int h = idx & 7, n = idx >> 3;
    const float4* hp = (const float4*)(Hm + (size_t)n * CC + h * DD);
    const float4* ap = (const float4*)(a + h * DD);
    float s = 0.f;
#pragma unroll
    for (int j = 0; j < 4; j++) {
        float4 x = hp[j], w = ap[j];
        s += x.x * w.x + x.y * w.y + x.z * w.z + x.w * w.w;
    }
    out[idx] = s;
}

__global__ void alpha3_kernel(const float* __restrict__ Hm,
                              const float* __restrict__ a1, const float* __restrict__ a2,
                              const float* __restrict__ a3,
                              float* __restrict__ o1, float* __restrict__ o2,
                              float* __restrict__ o3, int N) {
    __shared__ float s1[CC], s2[CC], s3[CC];
    if (threadIdx.x < CC) {
        s1[threadIdx.x] = a1[threadIdx.x];
        s2[threadIdx.x] = a2[threadIdx.x];
        s3[threadIdx.x] = a3[threadIdx.x];
    }
    __syncthreads();
    int idx = blockIdx.x * blockDim.x + threadIdx.x;
    if (idx >= N * HH) return;
    int h = idx & 7, n = idx >> 3;
    const float4* hp = (const float4*)(Hm + (size_t)n * CC + h * DD);
    const float4* p1 = (const float4*)(s1 + h * DD);
    const float4* p2 = (const float4*)(s2 + h * DD);
    const float4* p3 = (const float4*)(s3 + h * DD);
    float r1 = 0.f, r2 = 0.f, r3 = 0.f;
#pragma unroll
    for (int j = 0; j < 4; j++) {
        float4 x = hp[j];
        float4 w1 = p1[j], w2 = p2[j], w3 = p3[j];
        r1 += x.x * w1.x + x.y * w1.y + x.z * w1.z + x.w * w1.w;
        r2 += x.x * w2.x + x.y * w2.y + x.z * w2.z + x.w * w2.w;
        r3 += x.x * w3.x + x.y * w3.y + x.z * w3.z + x.w * w3.w;
    }
    o1[idx] = r1; o2[idx] = r2; o3[idx] = r3;
}

// ---------------- edge pass 1: alpha + leaky relu + segment max ----------------
__global__ void edge_alpha_max_kernel(const int* __restrict__ edge,
                                      const float* __restrict__ as,
                                      const float* __restrict__ ad,
                                      float* __restrict__ alpha_e,
                                      unsigned* __restrict__ segmax) {
    int idx = blockIdx.x * blockDim.x + threadIdx.x;
    if (idx >= EE * HH) return;
    int e = idx >> 3, h = idx & 7;
    int src = edge[e];
    int dst = edge[EE + e];
    float a = as[src * HH + h] + ad[dst * HH + h];
    a = (a >= 0.f) ? a : 0.2f * a;
    alpha_e[idx] = a;
    atomicMax(&segmax[dst * HH + h], fenc(a));
}

// ---------------- edge pass 2: exp + denom ----------------
__global__ void edge_exp_kernel(const int* __restrict__ edge,
                                float* __restrict__ alpha_e,
                                const unsigned* __restrict__ segmax,
                                float* __restrict__ denom) {
    int idx = blockIdx.x * blockDim.x + threadIdx.x;
    if (idx >= EE * HH) return;
    int e = idx >> 3, h = idx & 7;
    int dst = edge[EE + e];
    float m = fdec(segmax[dst * HH + h]);
    float ex = __expf(alpha_e[idx] - m);
    alpha_e[idx] = ex;
    atomicAdd(&denom[dst * HH + h], ex);
}

// ---------------- edge pass 3: weighted aggregate (warp per edge) ----------------
__global__ void edge_agg_kernel(const int* __restrict__ edge,
                                const float* __restrict__ Hsrc,
                                const float* __restrict__ alpha_e,
                                const float* __restrict__ denom,
                                float* __restrict__ outp) {
    int g = blockIdx.x * blockDim.x + threadIdx.x;
    int e = g >> 5;
    int lane = g & 31;
    if (e >= EE) return;
    int src = edge[e];
    int dst = edge[EE + e];
    int h = lane >> 2;
    float attn = alpha_e[e * HH + h] / denom[dst * HH + h];
    float4 hv = ((const float4*)(Hsrc + (size_t)src * CC))[lane];
    float* o = outp + (size_t)dst * CC + lane * 4;
    atomicAdd(o + 0, hv.x * attn);
    atomicAdd(o + 1, hv.y * attn);
    atomicAdd(o + 2, hv.z * attn);
    atomicAdd(o + 3, hv.w * attn);
}

// ---------------- semantic attention: wsum[r] = sum_n tanh(relu(out_r[n]) @ kW + kb) . q ----------------
__global__ void semantic_kernel(const float* __restrict__ kW,
                                const float* __restrict__ kb,
                                const float* __restrict__ q) {
    const float* A = g_out01 + (size_t)blockIdx.y * NP * CC;
    __shared__ float As[16][68];
    __shared__ float Bs[16][128];
    __shared__ float red[256];
    int tid = threadIdx.x;
    int tx = tid & 31, ty = tid >> 5;
    int row0 = blockIdx.x * 64;

    float acc[8][4];
#pragma unroll
    for (int m = 0; m < 8; m++)
#pragma unroll
        for (int n = 0; n < 4; n++) acc[m][n] = 0.f;

    int ar = tid >> 2, ak0 = (tid & 3) * 4;
    int bk = tid >> 4, bc0 = (tid & 15) * 8;

    for (int k0 = 0; k0 < CC; k0 += 16) {
        int grow = row0 + ar;
        float4 av = make_float4(0.f, 0.f, 0.f, 0.f);
        if (grow < NP)
            av = *(const float4*)(A + (size_t)grow * CC + k0 + ak0);
        As[ak0 + 0][ar] = fmaxf(av.x, 0.f);
        As[ak0 + 1][ar] = fmaxf(av.y, 0.f);
        As[ak0 + 2][ar] = fmaxf(av.z, 0.f);
        As[ak0 + 3][ar] = fmaxf(av.w, 0.f);

        const float* wp = kW + (size_t)(k0 + bk) * CC + bc0;
        float4 bv0 = *(const float4*)(wp);
        float4 bv1 = *(const float4*)(wp + 4);
        *(float4*)&Bs[bk][bc0] = bv0;
        *(float4*)&Bs[bk][bc0 + 4] = bv1;
        __syncthreads();

#pragma unroll
        for (int kk = 0; kk < 16; kk++) {
            float4 b4 = *(const float4*)&Bs[kk][tx * 4];
            float a[8];
#pragma unroll
            for (int m = 0; m < 8; m++) a[m] = As[kk][ty * 8 + m];
#pragma unroll
            for (int m = 0; m < 8; m++) {
                acc[m][0] += a[m] * b4.x;
                acc[m][1] += a[m] * b4.y;
                acc[m][2] += a[m] * b4.z;
                acc[m][3] += a[m] * b4.w;
            }
        }
        __syncthreads();
    }

    float4 kbv = *(const float4*)(kb + tx * 4);
    float4 qv = *(const float4*)(q + tx * 4);
    float part = 0.f;
#pragma unroll
    for (int m = 0; m < 8; m++) {
        int grow = row0 + ty * 8 + m;
        if (grow < NP) {
            part += tanhf(acc[m][0] + kbv.x) * qv.x;
            part += tanhf(acc[m][1] + kbv.y) * qv.y;
            part += tanhf(acc[m][2] + kbv.z) * qv.z;
            part += tanhf(acc[m][3] + kbv.w) * qv.w;
        }
    }
    red[tid] = part;
    __syncthreads();
    for (int s = 128; s > 0; s >>= 1) {
        if (tid < s) red[tid] += red[tid + s];
        __syncthreads();
    }
    if (tid == 0) atomicAdd(&g_wsum[blockIdx.y], red[0]);
}

__global__ void beta_kernel() {
    float w0 = g_wsum[0] / (float)NP;
    float w1 = g_wsum[1] / (float)NP;
    float m = fmaxf(w0, w1);
    float e0 = expf(w0 - m), e1 = expf(w1 - m);
    float s = e0 + e1;
    g_beta[0] = e0 / s;
    g_beta[1] = e1 / s;
}

// ---------------- per-channel stats of combined output ----------------
#define STAT_ROWS 512
__global__ void stats_kernel() {
    int c = threadIdx.x;            // 0..127
    float b0 = g_beta[0], b1 = g_beta[1];
    const float* o0 = g_out01;
    const float* o1 = g_out01 + (size_t)NP * CC;
    int r0 = blockIdx.x * STAT_ROWS;
    int r1 = r0 + STAT_ROWS; if (r1 > NP) r1 = NP;
    float s1 = 0.f, s2 = 0.f;
    for (int r = r0; r < r1; r++) {
        float v = b0 * fmaxf(o0[(size_t)r * CC + c], 0.f)
                + b1 * fmaxf(o1[(size_t)r * CC + c], 0.f);
        s1 += v;
        s2 += v * v;
    }
    atomicAdd(&g_S1[c], s1);
    atomicAdd(&g_S2[c], s2);
}

__global__ void normparam_kernel(const float* __restrict__ norm_w,
                                 const float* __restrict__ norm_b,
                                 const float* __restrict__ norm_ms) {
    int c = threadIdx.x;
    float mean = g_S1[c] / (float)NP;
    float eo2 = g_S2[c] / (float)NP;
    float mm = mean * norm_ms[c];
    float var = eo2 - 2.f * mm * mean + mm * mm;
    float A = norm_w[c] * rsqrtf(var + EPSV);
    g_nA[c] = A;
    g_nB[c] = norm_b[c] - mm * A;
}

// ---------------- fused normalize + classifier: y = norm(out) @ lin_W + lin_b ----------------
__global__ void final_kernel(const float* __restrict__ linW,
                             const float* __restrict__ linb,
                             float* __restrict__ y) {
    __shared__ float rowbuf[16][CC];
    __shared__ float lw[CC * OUTC];
    __shared__ float lb[OUTC];
    int tid = threadIdx.x;
    for (int i = tid; i < CC * OUTC; i += 256) lw[i] = linW[i];
    if (tid < OUTC) lb[tid] = linb[tid];
    float b0 = g_beta[0], b1 = g_beta[1];
    const float* o0 = g_out01;
    const float* o1 = g_out01 + (size_t)NP * CC;
    int nrow0 = blockIdx.x * 16;
#pragma unroll
    for (int j = 0; j < 8; j++) {
        int i = tid + j * 256;
        int r = i >> 7, c = i & 127;
        int gr = nrow0 + r;
        float v = 0.f;
        if (gr < NP) {
            v = b0 * fmaxf(o0[(size_t)gr * CC + c], 0.f)
              + b1 * fmaxf(o1[(size_t)gr * CC + c], 0.f);
            v = v * g_nA[c] + g_nB[c];
        }
        rowbuf[r][c] = v;
    }
    __syncthreads();
    int r = tid >> 4, o = tid & 15;
    int gr = nrow0 + r;
    if (gr < NP) {
        float s = lb[o];
#pragma unroll
        for (int c = 0; c < CC; c++) s += rowbuf[r][c] * lw[c * OUTC + o];
        y[(size_t)gr * OUTC + o] = s;
    }
}

// ---------------- launch ----------------
extern "C" void kernel_launch(void* const* d_in, const int* in_sizes, int n_in,
                              void* d_out, int out_size) {
    const float* x_author = (const float*)d_in[0];
    const float* x_paper  = (const float*)d_in[1];
    const float* W_a      = (const float*)d_in[2];
    const float* b_a      = (const float*)d_in[3];
    const float* W_p      = (const float*)d_in[4];
    const float* b_p      = (const float*)d_in[5];
    const float* att_src_ap = (const float*)d_in[6];
    const float* att_dst_ap = (const float*)d_in[7];
    const float* att_src_pp = (const float*)d_in[8];
    const float* att_dst_pp = (const float*)d_in[9];
    const float* k_W      = (const float*)d_in[10];
    const float* k_b      = (const float*)d_in[11];
    const float* q        = (const float*)d_in[12];
    const float* norm_w   = (const float*)d_in[13];
    const float* norm_b   = (const float*)d_in[14];
    const float* norm_ms  = (const float*)d_in[15];
    const float* lin_W    = (const float*)d_in[16];
    const float* lin_b    = (const float*)d_in[17];
    const int*   edge_ap  = (const int*)d_in[18];
    const int*   edge_pp  = (const int*)d_in[19];
    float* y = (float*)d_out;

    float *p_h_a, *p_h_p, *p_as_ap, *p_ad_ap, *p_as_pp, *p_ad_pp;
    float *p_alpha_ap, *p_alpha_pp, *p_denom, *p_out;
    unsigned* p_segmax;
    cudaGetSymbolAddress((void**)&p_h_a, g_h_a);
    cudaGetSymbolAddress((void**)&p_h_p, g_h_p);
    cudaGetSymbolAddress((void**)&p_as_ap, g_as_ap);
    cudaGetSymbolAddress((void**)&p_ad_ap, g_ad_ap);
    cudaGetSymbolAddress((void**)&p_as_pp, g_as_pp);
    cudaGetSymbolAddress((void**)&p_ad_pp, g_ad_pp);
    cudaGetSymbolAddress((void**)&p_alpha_ap, g_alpha_ap);
    cudaGetSymbolAddress((void**)&p_alpha_pp, g_alpha_pp);
    cudaGetSymbolAddress((void**)&p_segmax, g_segmax);
    cudaGetSymbolAddress((void**)&p_denom, g_denom);
    cudaGetSymbolAddress((void**)&p_out, g_out01);

    // 0. init accumulators
    init_kernel<<<2048, 256>>>();

    // 1. projections
    gemm_proj_kernel<FA><<<(NA + 63) / 64, 256>>>(x_author, W_a, b_a, p_h_a, NA);
    gemm_proj_kernel<FP><<<(NP + 63) / 64, 256>>>(x_paper, W_p, b_p, p_h_p, NP);

    // 2. attention logits per node
    alpha1_kernel<<<(NA * HH + 255) / 256, 256>>>(p_h_a, att_src_ap, p_as_ap, NA);
    alpha3_kernel<<<(NP * HH + 255) / 256, 256>>>(p_h_p, att_dst_ap, att_src_pp, att_dst_pp,
                                                  p_ad_ap, p_as_pp, p_ad_pp, NP);

    // 3. edge softmax passes (both edge types)
    int eb = (EE * HH + 255) / 256;
    edge_alpha_max_kernel<<<eb, 256>>>(edge_ap, p_as_ap, p_ad_ap, p_alpha_ap, p_segmax);
    edge_alpha_max_kernel<<<eb, 256>>>(edge_pp, p_as_pp, p_ad_pp, p_alpha_pp, p_segmax + NP * HH);
    edge_exp_kernel<<<eb, 256>>>(edge_ap, p_alpha_ap, p_segmax, p_denom);
    edge_exp_kernel<<<eb, 256>>>(edge_pp, p_alpha_pp, p_segmax + NP * HH, p_denom + NP * HH);

    // 4. weighted aggregation (warp per edge)
    int ab = (EE * 32 + 255) / 256;
    edge_agg_kernel<<<ab, 256>>>(edge_ap, p_h_a, p_alpha_ap, p_denom, p_out);
    edge_agg_kernel<<<ab, 256>>>(edge_pp, p_h_p, p_alpha_pp, p_denom + NP * HH,
                                 p_out + (size_t)NP * CC);

    // 5. semantic attention
    dim3 sgrid((NP + 63) / 64, 2);
    semantic_kernel<<<sgrid, 256>>>(k_W, k_b, q);
    beta_kernel<<<1, 1>>>();

    // 6. GraphNorm stats + params
    stats_kernel<<<(NP + STAT_ROWS - 1) / STAT_ROWS, CC>>>();
    normparam_kernel<<<1, CC>>>(norm_w, norm_b, norm_ms);

    // 7. normalize + classify
    final_kernel<<<(NP + 15) / 16, 256>>>(lin_W, lin_b, y);
}

// round 2
// speedup vs baseline: 1.3773x; 1.3773x over previous
#include <cuda_runtime.h>
#include <math.h>

#define NA 50000
#define NP 50000
#define EE 600000
#define HH 8
#define DD 16
#define CC 128
#define OUTC 16
#define FA 256
#define FP 128
#define EPSV 1e-5f

// ---------------- device scratch (static, no allocation) ----------------
__device__ float    g_h_a[(size_t)NA * CC];
__device__ float    g_h_p[(size_t)NP * CC];
__device__ float    g_as_ap[NA * HH];
__device__ float    g_ad_ap[NP * HH];
__device__ float    g_as_pp[NP * HH];
__device__ float    g_ad_pp[NP * HH];
__device__ float    g_attn_ap[(size_t)EE * HH];   // sorted-order edge weights
__device__ float    g_attn_pp[(size_t)EE * HH];
__device__ int      g_cnt[2 * NP];
__device__ int      g_cur[2 * NP];
__device__ int      g_rowptr[2 * (NP + 1)];
__device__ int      g_srcs[2 * (size_t)EE];       // src ids sorted by dst
__device__ float    g_out01[2 * (size_t)NP * CC]; // [r][n][c]
__device__ float    g_wsum[2];
__device__ float    g_beta[2];
__device__ float    g_S1[CC];
__device__ float    g_S2[CC];
__device__ float    g_nA[CC];
__device__ float    g_nB[CC];

// ---------------- init: re-zero small accumulators + histogram every call ----------------
__global__ void init_kernel() {
    int idx = blockIdx.x * blockDim.x + threadIdx.x;
    int stride = gridDim.x * blockDim.x;
    for (int i = idx; i < 2 * NP; i += stride) g_cnt[i] = 0;
    if (idx < CC) { g_S1[idx] = 0.f; g_S2[idx] = 0.f; }
    if (idx < 2)  g_wsum[idx] = 0.f;
}

// ---------------- CSR build: histogram ----------------
__global__ void hist_kernel(const int* __restrict__ e_ap, const int* __restrict__ e_pp) {
    int idx = blockIdx.x * blockDim.x + threadIdx.x;
    if (idx >= 2 * EE) return;
    int t = (idx >= EE);
    int e = idx - t * EE;
    const int* ed = t ? e_pp : e_ap;
    int dst = ed[EE + e];
    atomicAdd(&g_cnt[t * NP + dst], 1);
}

// ---------------- CSR build: single-block scan per type ----------------
#define SCAN_T 1024
#define SCAN_CHUNK 49   // 49*1024 = 50176 >= 50000
__global__ void scan_kernel() {
    int t = blockIdx.x;          // edge type
    int tid = threadIdx.x;
    const int* cnt = g_cnt + t * NP;
    int* rowptr = g_rowptr + t * (NP + 1);
    int* cur = g_cur + t * NP;

    int lo = tid * SCAN_CHUNK;
    int hi = lo + SCAN_CHUNK; if (hi > NP) hi = NP;
    int tsum = 0;
    for (int i = lo; i < hi; i++) tsum += cnt[i];

    __shared__ int sh[SCAN_T];
    sh[tid] = tsum;
    __syncthreads();
    for (int off = 1; off < SCAN_T; off <<= 1) {
        int v = (tid >= off) ? sh[tid - off] : 0;
        __syncthreads();
        sh[tid] += v;
        __syncthreads();
    }
    int running = sh[tid] - tsum;   // exclusive prefix
    for (int i = lo; i < hi; i++) {
        rowptr[i] = running;
        cur[i] = running;
        running += cnt[i];
    }
    if (tid == 0) rowptr[NP] = EE;
}

// ---------------- CSR build: scatter src ids by dst ----------------
__global__ void scatter_kernel(const int* __restrict__ e_ap, const int* __restrict__ e_pp) {
    int idx = blockIdx.x * blockDim.x + threadIdx.x;
    if (idx >= 2 * EE) return;
    int t = (idx >= EE);
    int e = idx - t * EE;
    const int* ed = t ? e_pp : e_ap;
    int src = ed[e];
    int dst = ed[EE + e];
    int pos = atomicAdd(&g_cur[t * NP + dst], 1);
    g_srcs[(size_t)t * EE + pos] = src;
}

// ---------------- tiled fp32 GEMM: [N, KDIM] x [KDIM, 128] + bias ----------------
template <int KDIM>
__global__ void gemm_proj_kernel(const float* __restrict__ X,
                                 const float* __restrict__ W,
                                 const float* __restrict__ bias,
                                 float* __restrict__ out, int Nrows) {
    __shared__ float As[16][68];
    __shared__ float Bs[16][128];
    int tid = threadIdx.x;
    int tx = tid & 31, ty = tid >> 5;
    int row0 = blockIdx.x * 64;

    float acc[8][4];
#pragma unroll
    for (int m = 0; m < 8; m++)
#pragma unroll
        for (int n = 0; n < 4; n++) acc[m][n] = 0.f;

    int ar = tid >> 2;
    int ak0 = (tid & 3) * 4;
    int bk = tid >> 4;
    int bc0 = (tid & 15) * 8;

    for (int k0 = 0; k0 < KDIM; k0 += 16) {
        int grow = row0 + ar;
        float4 av = make_float4(0.f, 0.f, 0.f, 0.f);
        if (grow < Nrows)
            av = *(const float4*)(X + (size_t)grow * KDIM + k0 + ak0);
        As[ak0 + 0][ar] = av.x; As[ak0 + 1][ar] = av.y;
        As[ak0 + 2][ar] = av.z; As[ak0 + 3][ar] = av.w;

        const float* wp = W + (size_t)(k0 + bk) * CC + bc0;
        float4 bv0 = *(const float4*)(wp);
        float4 bv1 = *(const float4*)(wp + 4);
        *(float4*)&Bs[bk][bc0] = bv0;
        *(float4*)&Bs[bk][bc0 + 4] = bv1;
        __syncthreads();

#pragma unroll
        for (int kk = 0; kk < 16; kk++) {
            float4 b4 = *(const float4*)&Bs[kk][tx * 4];
            float a[8];
#pragma unroll
            for (int m = 0; m < 8; m++) a[m] = As[kk][ty * 8 + m];
#pragma unroll
            for (int m = 0; m < 8; m++) {
                acc[m][0] += a[m] * b4.x;
                acc[m][1] += a[m] * b4.y;
                acc[m][2] += a[m] * b4.z;
                acc[m][3] += a[m] * b4.w;
            }
        }
        __syncthreads();
    }

    float4 bb = *(const float4*)(bias + tx * 4);
#pragma unroll
    for (int m = 0; m < 8; m++) {
        int grow = row0 + ty * 8 + m;
        if (grow < Nrows) {
            float4 v = make_float4(acc[m][0] + bb.x, acc[m][1] + bb.y,
                                   acc[m][2] + bb.z, acc[m][3] + bb.w);
            *(float4*)(out + (size_t)grow * CC + tx * 4) = v;
        }
    }
}

// ---------------- per-node-head attention logits ----------------
__global__ void alpha1_kernel(const float* __restrict__ Hm, const float* __restrict__ att,
                              float* __restrict__ out, int N) {
    __shared__ float a[CC];
    if (threadIdx.x < CC) a[threadIdx.x] = att[threadIdx.x];
    __syncthreads();
    int idx = blockIdx.x * blockDim.x + threadIdx.x;
    if (idx >= N * HH) return;
    int h = idx & 7, n = idx >> 3;
    const float4* hp = (const float4*)(Hm + (size_t)n * CC + h * DD);
    const float4* ap = (const float4*)(a + h * DD);
    float s = 0.f;
#pragma unroll
    for (int j = 0; j < 4; j++) {
        float4 x = hp[j], w = ap[j];
        s += x.x * w.x + x.y * w.y + x.z * w.z + x.w * w.w;
    }
    out[idx] = s;
}

__global__ void alpha3_kernel(const float* __restrict__ Hm,
                              const float* __restrict__ a1, const float* __restrict__ a2,
                              const float* __restrict__ a3,
                              float* __restrict__ o1, float* __restrict__ o2,
                              float* __restrict__ o3, int N) {
    __shared__ float s1[CC], s2[CC], s3[CC];
    if (threadIdx.x < CC) {
        s1[threadIdx.x] = a1[threadIdx.x];
        s2[threadIdx.x] = a2[threadIdx.x];
        s3[threadIdx.x] = a3[threadIdx.x];
    }
    __syncthreads();
    int idx = blockIdx.x * blockDim.x + threadIdx.x;
    if (idx >= N * HH) return;
    int h = idx & 7, n = idx >> 3;
    const float4* hp = (const float4*)(Hm + (size_t)n * CC + h * DD);
    const float4* p1 = (const float4*)(s1 + h * DD);
    const float4* p2 = (const float4*)(s2 + h * DD);
    const float4* p3 = (const float4*)(s3 + h * DD);
    float r1 = 0.f, r2 = 0.f, r3 = 0.f;
#pragma unroll
    for (int j = 0; j < 4; j++) {
        float4 x = hp[j];
        float4 w1 = p1[j], w2 = p2[j], w3 = p3[j];
        r1 += x.x * w1.x + x.y * w1.y + x.z * w1.z + x.w * w1.w;
        r2 += x.x * w2.x + x.y * w2.y + x.z * w2.z + x.w * w2.w;
        r3 += x.x * w3.x + x.y * w3.y + x.z * w3.z + x.w * w3.w;
    }
    o1[idx] = r1; o2[idx] = r2; o3[idx] = r3;
}

// ---------------- fused edge softmax + aggregation (warp per dst node) ----------------
__device__ __forceinline__ float warp_max8(float v) {
#pragma unroll
    for (int o = 16; o; o >>= 1) v = fmaxf(v, __shfl_xor_sync(0xFFFFFFFFu, v, o));
    return v;
}
__device__ __forceinline__ float warp_sum8(float v) {
#pragma unroll
    for (int o = 16; o; o >>= 1) v += __shfl_xor_sync(0xFFFFFFFFu, v, o);
    return v;
}

__global__ void edge_fused_kernel(const int* __restrict__ rowptr,
                                  const int* __restrict__ srcs,
                                  const float* __restrict__ as,
                                  const float* __restrict__ ad,
                                  float* __restrict__ attn,
                                  const float* __restrict__ Hsrc,
                                  float* __restrict__ outp) {
    __shared__ float sh_inv[8][8];  // [warp][head]
    int warp = threadIdx.x >> 5;
    int lane = threadIdx.x & 31;
    int dst = blockIdx.x * 8 + warp;
    if (dst >= NP) return;

    int base = rowptr[dst];
    int deg = rowptr[dst + 1] - base;

    float* ow = outp + (size_t)dst * CC;
    if (deg == 0) {
        *(float4*)(ow + lane * 4) = make_float4(0.f, 0.f, 0.f, 0.f);
        return;
    }

    // broadcast load of dst logits
    float4 adv0 = *(const float4*)(ad + dst * HH);
    float4 adv1 = *(const float4*)(ad + dst * HH + 4);
    float advs[8] = {adv0.x, adv0.y, adv0.z, adv0.w, adv1.x, adv1.y, adv1.z, adv1.w};

    // ---- phase A: per-head max over incoming edges ----
    float mx[8];
#pragma unroll
    for (int h = 0; h < 8; h++) mx[h] = -1e30f;
    for (int i = lane; i < deg; i += 32) {
        int s = srcs[base + i];
        float4 a0 = *(const float4*)(as + s * HH);
        float4 a1 = *(const float4*)(as + s * HH + 4);
        float al[8] = {a0.x, a0.y, a0.z, a0.w, a1.x, a1.y, a1.z, a1.w};
#pragma unroll
        for (int h = 0; h < 8; h++) {
            float v = al[h] + advs[h];
            v = (v >= 0.f) ? v : 0.2f * v;
            mx[h] = fmaxf(mx[h], v);
        }
    }
#pragma unroll
    for (int h = 0; h < 8; h++) mx[h] = warp_max8(mx[h]);

    // ---- phase B: exp, denom, store sorted-order weights ----
    float dn[8];
#pragma unroll
    for (int h = 0; h < 8; h++) dn[h] = 0.f;
    for (int i = lane; i < deg; i += 32) {
        int s = srcs[base + i];
        float4 a0 = *(const float4*)(as + s * HH);
        float4 a1 = *(const float4*)(as + s * HH + 4);
        float al[8] = {a0.x, a0.y, a0.z, a0.w, a1.x, a1.y, a1.z, a1.w};
        float ex[8];
#pragma unroll
        for (int h = 0; h < 8; h++) {
            float v = al[h] + advs[h];
            v = (v >= 0.f) ? v : 0.2f * v;
            float e = __expf(v - mx[h]);
            ex[h] = e;
            dn[h] += e;
        }
        float* ap = attn + (size_t)(base + i) * HH;
        *(float4*)(ap) = make_float4(ex[0], ex[1], ex[2], ex[3]);
        *(float4*)(ap + 4) = make_float4(ex[4], ex[5], ex[6], ex[7]);
    }
#pragma unroll
    for (int h = 0; h < 8; h++) dn[h] = warp_sum8(dn[h]);
    if (lane < 8) sh_inv[warp][lane] = 1.f / dn[lane];
    __syncwarp();

    // ---- phase C: serial edge loop, register accumulation of 4 channels/lane ----
    int myh = lane >> 2;
    float inv = sh_inv[warp][myh];
    float4 acc = make_float4(0.f, 0.f, 0.f, 0.f);
    for (int i = 0; i < deg; i++) {
        int s = srcs[base + i];                       // broadcast
        float w = attn[(size_t)(base + i) * HH + myh] * inv;
        float4 hv = *(const float4*)(Hsrc + (size_t)s * CC + lane * 4);
        acc.x += w * hv.x; acc.y += w * hv.y;
        acc.z += w * hv.z; acc.w += w * hv.w;
    }
    *(float4*)(ow + lane * 4) = acc;
}

// ---------------- semantic attention ----------------
__global__ void semantic_kernel(const float* __restrict__ kW,
                                const float* __restrict__ kb,
                                const float* __restrict__ q) {
    const float* A = g_out01 + (size_t)blockIdx.y * NP * CC;
    __shared__ float As[16][68];
    __shared__ float Bs[16][128];
    __shared__ float red[256];
    int tid = threadIdx.x;
    int tx = tid & 31, ty = tid >> 5;
    int row0 = blockIdx.x * 64;

    float acc[8][4];
#pragma unroll
    for (int m = 0; m < 8; m++)
#pragma unroll
        for (int n = 0; n < 4; n++) acc[m][n] = 0.f;

    int ar = tid >> 2, ak0 = (tid & 3) * 4;
    int bk = tid >> 4, bc0 = (tid & 15) * 8;

    for (int k0 = 0; k0 < CC; k0 += 16) {
        int grow = row0 + ar;
        float4 av = make_float4(0.f, 0.f, 0.f, 0.f);
        if (grow < NP)
            av = *(const float4*)(A + (size_t)grow * CC + k0 + ak0);
        As[ak0 + 0][ar] = fmaxf(av.x, 0.f);
        As[ak0 + 1][ar] = fmaxf(av.y, 0.f);
        As[ak0 + 2][ar] = fmaxf(av.z, 0.f);
        As[ak0 + 3][ar] = fmaxf(av.w, 0.f);

        const float* wp = kW + (size_t)(k0 + bk) * CC + bc0;
        float4 bv0 = *(const float4*)(wp);
        float4 bv1 = *(const float4*)(wp + 4);
        *(float4*)&Bs[bk][bc0] = bv0;
        *(float4*)&Bs[bk][bc0 + 4] = bv1;
        __syncthreads();

#pragma unroll
        for (int kk = 0; kk < 16; kk++) {
            float4 b4 = *(const float4*)&Bs[kk][tx * 4];
            float a[8];
#pragma unroll
            for (int m = 0; m < 8; m++) a[m] = As[kk][ty * 8 + m];
#pragma unroll
            for (int m = 0; m < 8; m++) {
                acc[m][0] += a[m] * b4.x;
                acc[m][1] += a[m] * b4.y;
                acc[m][2] += a[m] * b4.z;
                acc[m][3] += a[m] * b4.w;
            }
        }
        __syncthreads();
    }

    float4 kbv = *(const float4*)(kb + tx * 4);
    float4 qv = *(const float4*)(q + tx * 4);
    float part = 0.f;
#pragma unroll
    for (int m = 0; m < 8; m++) {
        int grow = row0 + ty * 8 + m;
        if (grow < NP) {
            part += tanhf(acc[m][0] + kbv.x) * qv.x;
            part += tanhf(acc[m][1] + kbv.y) * qv.y;
            part += tanhf(acc[m][2] + kbv.z) * qv.z;
            part += tanhf(acc[m][3] + kbv.w) * qv.w;
        }
    }
    red[tid] = part;
    __syncthreads();
    for (int s = 128; s > 0; s >>= 1) {
        if (tid < s) red[tid] += red[tid + s];
        __syncthreads();
    }
    if (tid == 0) atomicAdd(&g_wsum[blockIdx.y], red[0]);
}

__global__ void beta_kernel() {
    float w0 = g_wsum[0] / (float)NP;
    float w1 = g_wsum[1] / (float)NP;
    float m = fmaxf(w0, w1);
    float e0 = expf(w0 - m), e1 = expf(w1 - m);
    float s = e0 + e1;
    g_beta[0] = e0 / s;
    g_beta[1] = e1 / s;
}

// ---------------- per-channel stats of combined output ----------------
#define STAT_ROWS 512
__global__ void stats_kernel() {
    int c = threadIdx.x;
    float b0 = g_beta[0], b1 = g_beta[1];
    const float* o0 = g_out01;
    const float* o1 = g_out01 + (size_t)NP * CC;
    int r0 = blockIdx.x * STAT_ROWS;
    int r1 = r0 + STAT_ROWS; if (r1 > NP) r1 = NP;
    float s1 = 0.f, s2 = 0.f;
    for (int r = r0; r < r1; r++) {
        float v = b0 * fmaxf(o0[(size_t)r * CC + c], 0.f)
                + b1 * fmaxf(o1[(size_t)r * CC + c], 0.f);
        s1 += v;
        s2 += v * v;
    }
    atomicAdd(&g_S1[c], s1);
    atomicAdd(&g_S2[c], s2);
}

__global__ void normparam_kernel(const float* __restrict__ norm_w,
                                 const float* __restrict__ norm_b,
                                 const float* __restrict__ norm_ms) {
    int c = threadIdx.x;
    float mean = g_S1[c] / (float)NP;
    float eo2 = g_S2[c] / (float)NP;
    float mm = mean * norm_ms[c];
    float var = eo2 - 2.f * mm * mean + mm * mm;
    float A = norm_w[c] * rsqrtf(var + EPSV);
    g_nA[c] = A;
    g_nB[c] = norm_b[c] - mm * A;
}

// ---------------- fused normalize + classifier ----------------
__global__ void final_kernel(const float* __restrict__ linW,
                             const float* __restrict__ linb,
                             float* __restrict__ y) {
    __shared__ float rowbuf[16][CC];
    __shared__ float lw[CC * OUTC];
    __shared__ float lb[OUTC];
    int tid = threadIdx.x;
    for (int i = tid; i < CC * OUTC; i += 256) lw[i] = linW[i];
    if (tid < OUTC) lb[tid] = linb[tid];
    float b0 = g_beta[0], b1 = g_beta[1];
    const float* o0 = g_out01;
    const float* o1 = g_out01 + (size_t)NP * CC;
    int nrow0 = blockIdx.x * 16;
#pragma unroll
    for (int j = 0; j < 8; j++) {
        int i = tid + j * 256;
        int r = i >> 7, c = i & 127;
        int gr = nrow0 + r;
        float v = 0.f;
        if (gr < NP) {
            v = b0 * fmaxf(o0[(size_t)gr * CC + c], 0.f)
              + b1 * fmaxf(o1[(size_t)gr * CC + c], 0.f);
            v = v * g_nA[c] + g_nB[c];
        }
        rowbuf[r][c] = v;
    }
    __syncthreads();
    int r = tid >> 4, o = tid & 15;
    int gr = nrow0 + r;
    if (gr < NP) {
        float s = lb[o];
#pragma unroll
        for (int c = 0; c < CC; c++) s += rowbuf[r][c] * lw[c * OUTC + o];
        y[(size_t)gr * OUTC + o] = s;
    }
}

// ---------------- launch ----------------
extern "C" void kernel_launch(void* const* d_in, const int* in_sizes, int n_in,
                              void* d_out, int out_size) {
    const float* x_author = (const float*)d_in[0];
    const float* x_paper  = (const float*)d_in[1];
    const float* W_a      = (const float*)d_in[2];
    const float* b_a      = (const float*)d_in[3];
    const float* W_p      = (const float*)d_in[4];
    const float* b_p      = (const float*)d_in[5];
    const float* att_src_ap = (const float*)d_in[6];
    const float* att_dst_ap = (const float*)d_in[7];
    const float* att_src_pp = (const float*)d_in[8];
    const float* att_dst_pp = (const float*)d_in[9];
    const float* k_W      = (const float*)d_in[10];
    const float* k_b      = (const float*)d_in[11];
    const float* q        = (const float*)d_in[12];
    const float* norm_w   = (const float*)d_in[13];
    const float* norm_b   = (const float*)d_in[14];
    const float* norm_ms  = (const float*)d_in[15];
    const float* lin_W    = (const float*)d_in[16];
    const float* lin_b    = (const float*)d_in[17];
    const int*   edge_ap  = (const int*)d_in[18];
    const int*   edge_pp  = (const int*)d_in[19];
    float* y = (float*)d_out;

    float *p_h_a, *p_h_p, *p_as_ap, *p_ad_ap, *p_as_pp, *p_ad_pp;
    float *p_attn_ap, *p_attn_pp, *p_out;
    int *p_rowptr, *p_srcs;
    cudaGetSymbolAddress((void**)&p_h_a, g_h_a);
    cudaGetSymbolAddress((void**)&p_h_p, g_h_p);
    cudaGetSymbolAddress((void**)&p_as_ap, g_as_ap);
    cudaGetSymbolAddress((void**)&p_ad_ap, g_ad_ap);
    cudaGetSymbolAddress((void**)&p_as_pp, g_as_pp);
    cudaGetSymbolAddress((void**)&p_ad_pp, g_ad_pp);
    cudaGetSymbolAddress((void**)&p_attn_ap, g_attn_ap);
    cudaGetSymbolAddress((void**)&p_attn_pp, g_attn_pp);
    cudaGetSymbolAddress((void**)&p_rowptr, g_rowptr);
    cudaGetSymbolAddress((void**)&p_srcs, g_srcs);
    cudaGetSymbolAddress((void**)&p_out, g_out01);

    // 0. init small accumulators + histogram counters
    init_kernel<<<128, 256>>>();

    // 1. CSR build (both edge types)
    hist_kernel<<<(2 * EE + 255) / 256, 256>>>(edge_ap, edge_pp);
    scan_kernel<<<2, SCAN_T>>>();
    scatter_kernel<<<(2 * EE + 255) / 256, 256>>>(edge_ap, edge_pp);

    // 2. projections (overlap-independent of CSR build, same stream is fine)
    gemm_proj_kernel<FA><<<(NA + 63) / 64, 256>>>(x_author, W_a, b_a, p_h_a, NA);
    gemm_proj_kernel<FP><<<(NP + 63) / 64, 256>>>(x_paper, W_p, b_p, p_h_p, NP);

    // 3. attention logits per node
    alpha1_kernel<<<(NA * HH + 255) / 256, 256>>>(p_h_a, att_src_ap, p_as_ap, NA);
    alpha3_kernel<<<(NP * HH + 255) / 256, 256>>>(p_h_p, att_dst_ap, att_src_pp, att_dst_pp,
                                                  p_ad_ap, p_as_pp, p_ad_pp, NP);

    // 4. fused edge softmax + aggregation (no atomics)
    edge_fused_kernel<<<(NP + 7) / 8, 256>>>(p_rowptr, p_srcs,
                                             p_as_ap, p_ad_ap, p_attn_ap,
                                             p_h_a, p_out);
    edge_fused_kernel<<<(NP + 7) / 8, 256>>>(p_rowptr + (NP + 1), p_srcs + EE,
                                             p_as_pp, p_ad_pp, p_attn_pp,
                                             p_h_p, p_out + (size_t)NP * CC);

    // 5. semantic attention
    dim3 sgrid((NP + 63) / 64, 2);
    semantic_kernel<<<sgrid, 256>>>(k_W, k_b, q);
    beta_kernel<<<1, 1>>>();

    // 6. GraphNorm stats + params
    stats_kernel<<<(NP + STAT_ROWS - 1) / STAT_ROWS, CC>>>();
    normparam_kernel<<<1, CC>>>(norm_w, norm_b, norm_ms);

    // 7. normalize + classify
    final_kernel<<<(NP + 15) / 16, 256>>>(lin_W, lin_b, y);
}